// round 13
// baseline (speedup 1.0000x reference)
#include <cuda_runtime.h>
#include <math.h>

// Fixed problem shapes:
// feat0 [2,256,200,200] f32, feat1 [2,256,100,100], feat2 [2,256,50,50],
// feat3 [2,256,25,25], boxes [2,256,4] f32 -> out [512,256,7,7] f32.
#define KROIS   512
#define NC      256
#define OUTHW   7
#define NBINS   49
#define WARPS   8               // warps per block
#define CPW     4               // channels per warp (2 pair-iterations)
#define CPB     (WARPS * CPW)   // 32 channels per block
#define GRPS    (NC / CPB)      // 8 channel-groups per roi

__device__ __forceinline__ void prep_coord(float c, int size,
                                           int& lo, int& hi, float& l, float& h)
{
    c = fmaxf(c, 0.0f);
    lo = (int)c;
    if (lo >= size - 1) { lo = size - 1; hi = size - 1; }
    else                { hi = lo + 1; }
    l = c - (float)lo;
    h = 1.0f - l;
}

__global__ void __launch_bounds__(256, 6)
roi_align_warpauto_kernel(const float* __restrict__ f0,
                          const float* __restrict__ f1,
                          const float* __restrict__ f2,
                          const float* __restrict__ f3,
                          const float* __restrict__ boxes,
                          float* __restrict__ out)
{
    // per-warp tables: no block-wide synchronization anywhere
    __shared__ int4   s_yoff[WARPS][OUTHW];
    __shared__ float4 s_yw[WARPS][OUTHW];

    const int k    = blockIdx.x >> 3;          // roi  (GRPS = 8)
    const int grp  = blockIdx.x & (GRPS - 1);
    const int tid  = threadIdx.x;
    const int warp = tid >> 5;
    const int lane = tid & 31;

    // ---- per-roi scalars: all lanes redundantly (warp-uniform, ~25 instr) ----
    const float4 bx = __ldg((const float4*)boxes + k);
    const float x1 = bx.x, y1 = bx.y, x2 = bx.z, y2 = bx.w;

    float area = (x2 - x1) * (y2 - y1);
    float s    = sqrtf(area);
    float lvl  = floorf(4.0f + log2f(s / 224.0f) + 1e-6f);
    lvl = fminf(fmaxf(lvl, 2.0f), 5.0f);
    const int level = (int)lvl - 2;

    const float scales[4] = {0.25f, 0.125f, 0.0625f, 0.03125f};
    const int   dims[4]   = {200, 100, 50, 25};
    const float sc = scales[level];
    const int   W  = dims[level];

    const float x1s = x1 * sc, y1s = y1 * sc;
    const float x2s = x2 * sc, y2s = y2 * sc;
    const float bin_w = fmaxf(x2s - x1s, 1.0f) / (float)OUTHW;
    const float bin_h = fmaxf(y2s - y1s, 1.0f) / (float)OUTHW;

    // ---- y tables: lanes 0-6 of THIS warp, into per-warp smem ----
    if (lane < OUTHW) {
        int p = lane;
        float half = bin_h * 0.5f;
        int lo0, hi0, lo1, hi1; float l0, h0, l1, h1;
        prep_coord(y1s + (float)p * bin_h + 0.5f * half, W, lo0, hi0, l0, h0);
        prep_coord(y1s + (float)p * bin_h + 1.5f * half, W, lo1, hi1, l1, h1);
        s_yoff[warp][p] = make_int4(lo0 * W, hi0 * W, lo1 * W, hi1 * W);
        s_yw[warp][p]   = make_float4(h0, l0, h1, l1);
    }

    // ---- per-lane x corner: j = 4*pw + 2*ix + corner (lanes 28-31 mirror 27) ----
    const int j      = (lane < 28) ? lane : 27;
    const int si     = j >> 1;
    const int corner = j & 1;
    const int pwj    = si >> 1;
    const int ixj    = si & 1;

    float half_bw = bin_w * 0.5f;
    int xlo, xhi; float xl, xh;
    prep_coord(x1s + (float)pwj * bin_w + ((float)ixj + 0.5f) * half_bw, W,
               xlo, xhi, xl, xh);
    const int   xc = corner ? xhi : xlo;
    const float xw = 0.25f * (corner ? xl : xh);

    const float* feat;
    switch (level) {
        case 0:  feat = f0; break;
        case 1:  feat = f1; break;
        case 2:  feat = f2; break;
        default: feat = f3; break;
    }
    const int c0    = grp * CPB + warp * CPW;   // first of CPW adjacent channels
    const int b     = k >> 8;
    const int plane = W * W;
    const float* __restrict__ pb =
        feat + (size_t)((b * NC + c0) * W) * (size_t)W + xc;

    __syncwarp();   // y tables visible within the warp

    // store lane: lanes 0,4,...,24 write pw = lane>>2
    const bool wr  = (lane < 28) && ((lane & 3) == 0);
    const int  pwo = lane >> 2;
    size_t obase = (size_t)(k * NC + c0) * NBINS;

    #pragma unroll 1
    for (int pp = 0; pp < CPW / 2; pp++) {
        #pragma unroll
        for (int ch = 0; ch < 2; ch++) {
            const float* __restrict__ p = pb + ch * plane;

            // batch all 28 loads first (max MLP)
            float v[OUTHW][4];
            #pragma unroll
            for (int ph = 0; ph < OUTHW; ph++) {
                int4 ro = s_yoff[warp][ph];
                v[ph][0] = __ldg(p + ro.x);
                v[ph][1] = __ldg(p + ro.y);
                v[ph][2] = __ldg(p + ro.z);
                v[ph][3] = __ldg(p + ro.w);
            }

            // y-FMA, x-weight, then 4-lane butterfly sum; direct store
            #pragma unroll
            for (int ph = 0; ph < OUTHW; ph++) {
                float4 yw = s_yw[warp][ph];
                float a = (yw.x * v[ph][0] + yw.y * v[ph][1]
                         + yw.z * v[ph][2] + yw.w * v[ph][3]) * xw;
                a += __shfl_xor_sync(0xffffffffu, a, 1);
                a += __shfl_xor_sync(0xffffffffu, a, 2);
                if (wr) out[obase + ch * NBINS + ph * OUTHW + pwo] = a;
            }
        }
        pb    += 2 * plane;
        obase += 2 * NBINS;
    }
}

extern "C" void kernel_launch(void* const* d_in, const int* in_sizes, int n_in,
                              void* d_out, int out_size)
{
    const float* f0    = (const float*)d_in[0];
    const float* f1    = (const float*)d_in[1];
    const float* f2    = (const float*)d_in[2];
    const float* f3    = (const float*)d_in[3];
    const float* boxes = (const float*)d_in[4];
    float* out = (float*)d_out;

    const int blocks = KROIS * GRPS;   // 512 * 8 = 4096
    roi_align_warpauto_kernel<<<blocks, 256>>>(f0, f1, f2, f3, boxes, out);
}

// round 14
// speedup vs baseline: 1.0846x; 1.0846x over previous
#include <cuda_runtime.h>
#include <math.h>

// Fixed problem shapes:
// feat0 [2,256,200,200] f32, feat1 [2,256,100,100], feat2 [2,256,50,50],
// feat3 [2,256,25,25], boxes [2,256,4] f32 -> out [512,256,7,7] f32.
#define KROIS   512
#define NC      256
#define OUTHW   7
#define NBINS   49
#define WARPS   4               // warps per block (small blocks: cheap barriers)
#define CPW     4               // channels per warp (2 pair-iterations)
#define CPB     (WARPS * CPW)   // 16 channels per block
#define GRPS    (NC / CPB)      // 16 channel-groups per roi

__device__ __forceinline__ void prep_coord(float c, int size,
                                           int& lo, int& hi, float& l, float& h)
{
    c = fmaxf(c, 0.0f);
    lo = (int)c;
    if (lo >= size - 1) { lo = size - 1; hi = size - 1; }
    else                { hi = lo + 1; }
    l = c - (float)lo;
    h = 1.0f - l;
}

__global__ void __launch_bounds__(128, 12)
roi_align_w4_kernel(const float* __restrict__ f0,
                    const float* __restrict__ f1,
                    const float* __restrict__ f2,
                    const float* __restrict__ f3,
                    const float* __restrict__ boxes,
                    float* __restrict__ out)
{
    __shared__ int4   s_yoff[OUTHW];
    __shared__ float4 s_yw[OUTHW];
    __shared__ float  s_f[4];          // x1s, y1s, bin_w, bin_h
    __shared__ int    s_i[2];          // level, W

    const int k   = blockIdx.x >> 4;          // roi  (GRPS = 16)
    const int grp = blockIdx.x & (GRPS - 1);
    const int tid = threadIdx.x;

    // ---- setup: threads 0-6 redundantly compute scalars + own y-table entry ----
    if (tid < OUTHW) {
        const float4 bx = __ldg((const float4*)boxes + k);
        float x1 = bx.x, y1 = bx.y, x2 = bx.z, y2 = bx.w;

        float area = (x2 - x1) * (y2 - y1);
        float s    = sqrtf(area);
        float lvl  = floorf(4.0f + log2f(s / 224.0f) + 1e-6f);
        lvl = fminf(fmaxf(lvl, 2.0f), 5.0f);
        int level = (int)lvl - 2;

        const float scales[4] = {0.25f, 0.125f, 0.0625f, 0.03125f};
        const int   dims[4]   = {200, 100, 50, 25};
        float sc = scales[level];
        int   W  = dims[level];

        float x1s = x1 * sc, y1s = y1 * sc;
        float x2s = x2 * sc, y2s = y2 * sc;
        float bin_w = fmaxf(x2s - x1s, 1.0f) / (float)OUTHW;
        float bin_h = fmaxf(y2s - y1s, 1.0f) / (float)OUTHW;

        if (tid == 0) {
            s_f[0] = x1s; s_f[1] = y1s; s_f[2] = bin_w; s_f[3] = bin_h;
            s_i[0] = level; s_i[1] = W;
        }

        int p = tid;
        float half = bin_h * 0.5f;
        int lo0, hi0, lo1, hi1; float l0, h0, l1, h1;
        prep_coord(y1s + (float)p * bin_h + 0.5f * half, W, lo0, hi0, l0, h0);
        prep_coord(y1s + (float)p * bin_h + 1.5f * half, W, lo1, hi1, l1, h1);
        s_yoff[p] = make_int4(lo0 * W, hi0 * W, lo1 * W, hi1 * W);
        s_yw[p]   = make_float4(h0, l0, h1, l1);
    }
    __syncthreads();

    const int   level = s_i[0];
    const int   W     = s_i[1];
    const float x1s   = s_f[0];
    const float bin_w = s_f[2];

    const int warp = tid >> 5;
    const int lane = tid & 31;
    const int c0   = grp * CPB + warp * CPW;    // first of CPW adjacent channels
    const int b    = k >> 8;

    // ---- per-lane x corner: j = 4*pw + 2*ix + corner (lanes 28-31 mirror 27) ----
    const int j      = (lane < 28) ? lane : 27;
    const int si     = j >> 1;
    const int corner = j & 1;
    const int pwj    = si >> 1;
    const int ixj    = si & 1;

    float half_bw = bin_w * 0.5f;
    int xlo, xhi; float xl, xh;
    prep_coord(x1s + (float)pwj * bin_w + ((float)ixj + 0.5f) * half_bw, W,
               xlo, xhi, xl, xh);
    const int   xc = corner ? xhi : xlo;
    const float xw = 0.25f * (corner ? xl : xh);

    const float* feat;
    switch (level) {
        case 0:  feat = f0; break;
        case 1:  feat = f1; break;
        case 2:  feat = f2; break;
        default: feat = f3; break;
    }
    const int plane = W * W;
    const float* __restrict__ pb =
        feat + (size_t)((b * NC + c0) * W) * (size_t)W + xc;

    // store lane: lanes 0,4,...,24 write pw = lane>>2
    const bool wr  = (lane < 28) && ((lane & 3) == 0);
    const int  pwo = lane >> 2;
    size_t obase = (size_t)(k * NC + c0) * NBINS;

    #pragma unroll 1
    for (int pp = 0; pp < CPW / 2; pp++) {
        #pragma unroll
        for (int ch = 0; ch < 2; ch++) {
            const float* __restrict__ p = pb + ch * plane;

            // batch all 28 loads first (max MLP)
            float v[OUTHW][4];
            #pragma unroll
            for (int ph = 0; ph < OUTHW; ph++) {
                int4 ro = s_yoff[ph];
                v[ph][0] = __ldg(p + ro.x);
                v[ph][1] = __ldg(p + ro.y);
                v[ph][2] = __ldg(p + ro.z);
                v[ph][3] = __ldg(p + ro.w);
            }

            // y-FMA, x-weight, then 4-lane butterfly sum; direct store
            #pragma unroll
            for (int ph = 0; ph < OUTHW; ph++) {
                float4 yw = s_yw[ph];
                float a = (yw.x * v[ph][0] + yw.y * v[ph][1]
                         + yw.z * v[ph][2] + yw.w * v[ph][3]) * xw;
                a += __shfl_xor_sync(0xffffffffu, a, 1);
                a += __shfl_xor_sync(0xffffffffu, a, 2);
                if (wr) out[obase + ch * NBINS + ph * OUTHW + pwo] = a;
            }
        }
        pb    += 2 * plane;
        obase += 2 * NBINS;
    }
}

extern "C" void kernel_launch(void* const* d_in, const int* in_sizes, int n_in,
                              void* d_out, int out_size)
{
    const float* f0    = (const float*)d_in[0];
    const float* f1    = (const float*)d_in[1];
    const float* f2    = (const float*)d_in[2];
    const float* f3    = (const float*)d_in[3];
    const float* boxes = (const float*)d_in[4];
    float* out = (float*)d_out;

    const int blocks = KROIS * GRPS;   // 512 * 16 = 8192
    roi_align_w4_kernel<<<blocks, 128>>>(f0, f1, f2, f3, boxes, out);
}